// round 3
// baseline (speedup 1.0000x reference)
#include <cuda_runtime.h>
#include <mma.h>
#include <math.h>
#include <stdint.h>

using namespace nvcuda;

// ---------------- problem constants ----------------
#define BB 8
#define NN 1024
#define DV 768
#define DS 512
#define FF 768
#define HH 12
#define DH 64
#define KG 1280        // Dv + Ds
#define ROWS (BB*NN)   // 8192
#define SCALE 0.125f   // dh^-0.5
#define EPS 1e-5f

// ---------------- scratch (device globals; no allocation allowed) ----------------
__device__ float g_q[BB*FF];
__device__ float g_gw[BB*HH*DV];      // scale * gv[d] * wqk[b,h,d]
__device__ float g_S1[BB*HH];         // sum_d gw
__device__ float g_S0[BB*HH];         // scale * sum_d bv[d]*wqk
__device__ float g_gsem[BB*DV];       // sem @ Wg[:,768:].T + bg
__device__ float g_mu[ROWS];
__device__ float g_rstd[ROWS];
__device__ float g_scores[BB*HH*NN];
__device__ float g_w[BB*HH*NN];       // attn * rstd
__device__ float g_t[BB*HH];          // sum_n attn*rstd*mu
#define NCHUNK 32
__device__ float g_vbarp[NCHUNK*BB*HH*DV];
__device__ float g_vbar[BB*HH*DV];
__device__ float g_ctx[BB*FF];
__device__ float g_att[BB*DV];

// ---------------- generic helpers ----------------
__device__ __forceinline__ float warp_sum(float v) {
#pragma unroll
    for (int o = 16; o > 0; o >>= 1) v += __shfl_down_sync(0xffffffffu, v, o);
    return v;
}
__device__ __forceinline__ float warp_sum_all(float v) {
#pragma unroll
    for (int o = 16; o > 0; o >>= 1) v += __shfl_xor_sync(0xffffffffu, v, o);
    return v;
}
__device__ __forceinline__ float warp_max(float v) {
#pragma unroll
    for (int o = 16; o > 0; o >>= 1) v = fmaxf(v, __shfl_down_sync(0xffffffffu, v, o));
    return v;
}
__device__ __forceinline__ float block_sum256(float v, float* red) {
    int lane = threadIdx.x & 31, wid = threadIdx.x >> 5;
    __syncthreads();
    v = warp_sum(v);
    if (lane == 0) red[wid] = v;
    __syncthreads();
    if (wid == 0) {
        float x = (lane < 8) ? red[lane] : 0.f;
        x = warp_sum(x);
        if (lane == 0) red[0] = x;
    }
    __syncthreads();
    return red[0];
}
__device__ __forceinline__ float block_max256(float v, float* red) {
    int lane = threadIdx.x & 31, wid = threadIdx.x >> 5;
    __syncthreads();
    v = warp_max(v);
    if (lane == 0) red[wid] = v;
    __syncthreads();
    if (wid == 0) {
        float x = (lane < 8) ? red[lane] : -1e30f;
        x = warp_max(x);
        if (lane == 0) red[0] = x;
    }
    __syncthreads();
    return red[0];
}

#define CP16(dst, src)   asm volatile("cp.async.cg.shared.global [%0], [%1], 16;" :: "r"(dst), "l"(src) : "memory")
#define CP_COMMIT()      asm volatile("cp.async.commit_group;" ::: "memory")

__device__ __forceinline__ uint32_t smem_u32(const void* p) {
    uint32_t a;
    asm("{ .reg .u64 t; cvta.to.shared.u64 t, %1; cvt.u32.u64 %0, t; }" : "=r"(a) : "l"(p));
    return a;
}

// ---------------- K0a: semantic LN + q = sem_n @ Wq.T ----------------
__global__ __launch_bounds__(256) void k0a(const float* __restrict__ sem,
                                           const float* __restrict__ Wq,
                                           const float* __restrict__ gs,
                                           const float* __restrict__ bs) {
    int b = blockIdx.x;
    __shared__ float sm[DS];
    __shared__ float red[8];
    int tid = threadIdx.x, lane = tid & 31, wid = tid >> 5;
    float sum = 0.f, sq = 0.f;
    for (int i = tid; i < DS; i += 256) {
        float v = sem[b*DS + i];
        sm[i] = v; sum += v; sq += v*v;
    }
    sum = block_sum256(sum, red);
    sq  = block_sum256(sq, red);
    float mu = sum * (1.f/DS);
    float rstd = rsqrtf(sq * (1.f/DS) - mu*mu + EPS);
    for (int i = tid; i < DS; i += 256)
        sm[i] = (sm[i] - mu) * rstd * gs[i] + bs[i];
    __syncthreads();
    for (int f = wid; f < FF; f += 8) {
        float dot = 0.f;
        for (int s = lane; s < DS; s += 32) dot += sm[s] * Wq[(size_t)f*DS + s];
        dot = warp_sum(dot);
        if (lane == 0) g_q[b*FF + f] = dot;
    }
}

// ---------------- K0b: gw[b,h,:] = scale*gv*(q_h @ Wk_h), S1, S0 ----------------
__global__ __launch_bounds__(256) void k0b(const float* __restrict__ Wk,
                                           const float* __restrict__ gv,
                                           const float* __restrict__ bv) {
    int h = blockIdx.x, b = blockIdx.y;
    __shared__ float qh[DH];
    __shared__ float red[8];
    int tid = threadIdx.x;
    if (tid < DH) qh[tid] = g_q[b*FF + h*DH + tid];
    __syncthreads();
    float s1p = 0.f, s0p = 0.f;
    for (int d = tid; d < DV; d += 256) {
        float s = 0.f;
#pragma unroll 16
        for (int j = 0; j < DH; j++) s += qh[j] * Wk[(size_t)(h*DH + j)*DV + d];
        s *= SCALE;
        float gwv = gv[d] * s;
        g_gw[(b*HH + h)*DV + d] = gwv;
        s1p += gwv;
        s0p += bv[d] * s;
    }
    s1p = block_sum256(s1p, red);
    s0p = block_sum256(s0p, red);
    if (tid == 0) { g_S1[b*HH + h] = s1p; g_S0[b*HH + h] = s0p; }
}

// ---------------- K0c: gsem[b,:] = sem @ Wg[:,768:].T + bg ----------------
__global__ __launch_bounds__(256) void k0c(const float* __restrict__ sem,
                                           const float* __restrict__ Wg,
                                           const float* __restrict__ bg) {
    int b = blockIdx.x;
    __shared__ float sm[DS];
    int tid = threadIdx.x, lane = tid & 31, wid = tid >> 5;
    for (int i = tid; i < DS; i += 256) sm[i] = sem[b*DS + i];
    __syncthreads();
    for (int dv = wid; dv < DV; dv += 8) {
        float dot = 0.f;
        for (int s = lane; s < DS; s += 32) dot += sm[s] * Wg[(size_t)dv*KG + DV + s];
        dot = warp_sum(dot);
        if (lane == 0) g_gsem[b*DV + dv] = dot + bg[dv];
    }
}

// ---------------- K1: warp-per-row LN stats + scores (32 rows / block) ----------------
__global__ __launch_bounds__(256) void k1(const float* __restrict__ vis) {
    __shared__ float gw_s[HH*DV];   // 36 KB
    __shared__ float s1s[HH], s0s[HH];
    int tid = threadIdx.x, lane = tid & 31, wid = tid >> 5;
    int row0 = blockIdx.x * 32;
    int b = row0 >> 10;
    {
        const float4* gsrc = (const float4*)(g_gw + b*HH*DV);
        float4* gdst = (float4*)gw_s;
#pragma unroll
        for (int i = 0; i < 9; i++) gdst[tid + i*256] = gsrc[tid + i*256];
    }
    if (tid < HH) { s1s[tid] = g_S1[b*HH + tid]; s0s[tid] = g_S0[b*HH + tid]; }
    __syncthreads();
#pragma unroll
    for (int rr = 0; rr < 4; rr++) {
        int row = row0 + wid*4 + rr;
        const float4* x4 = (const float4*)(vis + (size_t)row * DV);
        float4 xv[6];
#pragma unroll
        for (int s = 0; s < 6; s++) xv[s] = x4[s*32 + lane];
        float sum = 0.f, sq = 0.f;
#pragma unroll
        for (int s = 0; s < 6; s++) {
            sum += xv[s].x + xv[s].y + xv[s].z + xv[s].w;
            sq  += xv[s].x*xv[s].x + xv[s].y*xv[s].y + xv[s].z*xv[s].z + xv[s].w*xv[s].w;
        }
        sum = warp_sum_all(sum);
        sq  = warp_sum_all(sq);
        float mu = sum * (1.f/DV);
        float rstd = rsqrtf(sq * (1.f/DV) - mu*mu + EPS);
        if (lane == 0) { g_mu[row] = mu; g_rstd[row] = rstd; }
        int n = row & (NN - 1);
#pragma unroll
        for (int h = 0; h < HH; h++) {
            const float4* g4 = (const float4*)(gw_s + h*DV);
            float dot = 0.f;
#pragma unroll
            for (int s = 0; s < 6; s++) {
                float4 gv4 = g4[s*32 + lane];
                dot += xv[s].x*gv4.x + xv[s].y*gv4.y + xv[s].z*gv4.z + xv[s].w*gv4.w;
            }
            dot = warp_sum(dot);
            if (lane == 0)
                g_scores[(b*HH + h)*NN + n] = rstd * (dot - mu*s1s[h]) + s0s[h];
        }
    }
}

// ---------------- K2: softmax over n; w = attn*rstd, t = sum attn*rstd*mu ----------------
__global__ __launch_bounds__(256) void k2() {
    int bh = blockIdx.x;
    int b = bh / HH;
    __shared__ float red[8];
    int tid = threadIdx.x;
    float loc[4];
    float mx = -1e30f;
#pragma unroll
    for (int i = 0; i < 4; i++) {
        loc[i] = g_scores[bh*NN + tid + i*256];
        mx = fmaxf(mx, loc[i]);
    }
    mx = block_max256(mx, red);
    float s = 0.f;
#pragma unroll
    for (int i = 0; i < 4; i++) { loc[i] = expf(loc[i] - mx); s += loc[i]; }
    s = block_sum256(s, red);
    float inv = 1.f / s;
    float tp = 0.f;
#pragma unroll
    for (int i = 0; i < 4; i++) {
        int n = tid + i*256;
        float a = loc[i] * inv;
        float rs = g_rstd[b*NN + n];
        float w = a * rs;
        g_w[bh*NN + n] = w;
        tp += w * g_mu[b*NN + n];
    }
    tp = block_sum256(tp, red);
    if (tid == 0) g_t[bh] = tp;
}

// ---------------- K3: per-chunk partial vbar (deterministic) ----------------
__global__ __launch_bounds__(768) void k3(const float* __restrict__ vis) {
    int chunk = blockIdx.x;     // 32 chunks of 32 tokens
    int b = blockIdx.y;
    int d = threadIdx.x;        // 768 threads = one per feature
    __shared__ float ws[HH][32];
    int n0 = chunk * 32;
    if (d < HH*32) {
        int h = d >> 5, j = d & 31;
        ws[h][j] = g_w[(b*HH + h)*NN + n0 + j];
    }
    __syncthreads();
    float acc[HH];
#pragma unroll
    for (int h = 0; h < HH; h++) acc[h] = 0.f;
    const float* base = vis + ((size_t)(b << 10) + n0) * DV + d;
#pragma unroll 4
    for (int j = 0; j < 32; j++) {
        float x = base[(size_t)j * DV];
#pragma unroll
        for (int h = 0; h < HH; h++) acc[h] += ws[h][j] * x;
    }
#pragma unroll
    for (int h = 0; h < HH; h++)
        g_vbarp[(size_t)chunk*(BB*HH*DV) + (b*HH + h)*DV + d] = acc[h];
}

// ---------------- K3b: reduce chunks ----------------
__global__ __launch_bounds__(1024) void k3b() {
    int i = blockIdx.x * 1024 + threadIdx.x;
    float s = 0.f;
#pragma unroll
    for (int c = 0; c < NCHUNK; c++) s += g_vbarp[(size_t)c*(BB*HH*DV) + i];
    g_vbar[i] = s;
}

// ---------------- K4a: ctx[b,f] = u[b,h,:] @ Wv[f,:] ----------------
__global__ __launch_bounds__(256) void k4a(const float* __restrict__ Wv,
                                           const float* __restrict__ gv,
                                           const float* __restrict__ bv) {
    int h = blockIdx.x, b = blockIdx.y;
    __shared__ float u[DV];
    int tid = threadIdx.x, lane = tid & 31, wid = tid >> 5;
    float t = g_t[b*HH + h];
    for (int d = tid; d < DV; d += 256)
        u[d] = gv[d] * (g_vbar[(b*HH + h)*DV + d] - t) + bv[d];
    __syncthreads();
    for (int j = wid; j < DH; j += 8) {
        int f = h*DH + j;
        float dot = 0.f;
        for (int d = lane; d < DV; d += 32) dot += u[d] * Wv[(size_t)f*DV + d];
        dot = warp_sum(dot);
        if (lane == 0) g_ctx[b*FF + f] = dot;
    }
}

// ---------------- K4b: attended[b,:] = ctx @ Wo.T + bo ----------------
__global__ __launch_bounds__(256) void k4b(const float* __restrict__ Wo,
                                           const float* __restrict__ bo) {
    int b = blockIdx.x;
    __shared__ float c[FF];
    int tid = threadIdx.x, lane = tid & 31, wid = tid >> 5;
    for (int i = tid; i < FF; i += 256) c[i] = g_ctx[b*FF + i];
    __syncthreads();
    for (int dv = wid; dv < DV; dv += 8) {
        float dot = 0.f;
        for (int f = lane; f < FF; f += 32) dot += c[f] * Wo[(size_t)dv*FF + f];
        dot = warp_sum(dot);
        if (lane == 0) g_att[b*DV + dv] = dot + bo[dv];
    }
}

// ---------------- K5: gate GEMM (wmma tf32) + fused sigmoid/residual epilogue ----------------
// out[r,c] = A[r,c] + sigmoid( sum_k A[r,k]*Wg[c,k] + gsem[b,c] ) * att[b,c]
// CTA tile M=128, N=128; K=768 in 24 tiles of 32. 2-stage cp.async double buffer.
// 8 warps in 2(M)x4(N) grid: each warp 64x32 via wmma m16n16k8 tf32 (4 m-frags x 2 n-frags).

#define K5_AS 40                 // smem row stride (32 data + 8 pad), floats
#define K5_TILE_BYTES (128*K5_AS*4)        // 20480
#define K5_A_OFF(stage) ((stage)*2*K5_TILE_BYTES)
#define K5_B_OFF(stage) ((stage)*2*K5_TILE_BYTES + K5_TILE_BYTES)
#define K5_PIPE_BYTES   (4*K5_TILE_BYTES)  // 81920
#define K5_CS 136                // C smem row stride
#define K5_SMEM_TOTAL K5_PIPE_BYTES        // > 128*136*4 = 69632, reused for C

__global__ void __launch_bounds__(256, 2)
k5(const float* __restrict__ A, const float* __restrict__ Wg, float* __restrict__ out) {
    extern __shared__ float smem[];
    uint32_t sbase = smem_u32(smem);
    int tid = threadIdx.x, wid = tid >> 5, lane = tid & 31;
    int rowBase = blockIdx.x * 128;
    int colBase = blockIdx.y * 128;
    int warp_m = wid >> 2;       // 0..1 -> 64 rows each
    int warp_n = wid & 3;        // 0..3 -> 32 cols each

    // per-thread cp.async slots: 4 x 16B for A, 4 x 16B for B per stage
    uint32_t dsto[4];
    const float* srcA[4];
    const float* srcB[4];
#pragma unroll
    for (int i = 0; i < 4; i++) {
        int idx = tid + i*256;           // 0..1023
        int row = idx >> 3, seg = idx & 7;
        dsto[i] = (uint32_t)((row*K5_AS + seg*4) * 4);
        srcA[i] = A  + (size_t)(rowBase + row)*DV + seg*4;
        srcB[i] = Wg + (size_t)(colBase + row)*KG + seg*4;
    }

    wmma::fragment<wmma::accumulator, 16, 16, 8, float> cf[4][2];
#pragma unroll
    for (int mi = 0; mi < 4; mi++)
#pragma unroll
        for (int ni = 0; ni < 2; ni++) wmma::fill_fragment(cf[mi][ni], 0.f);

    // prologue: stage 0
#pragma unroll
    for (int i = 0; i < 4; i++) {
        CP16(sbase + K5_A_OFF(0) + dsto[i], srcA[i]);
        CP16(sbase + K5_B_OFF(0) + dsto[i], srcB[i]);
    }
    CP_COMMIT();

    int buf = 0;
    for (int kt = 0; kt < 24; kt++) {
        if (kt + 1 < 24) {
#pragma unroll
            for (int i = 0; i < 4; i++) {
                CP16(sbase + K5_A_OFF(buf^1) + dsto[i], srcA[i] + (kt+1)*32);
                CP16(sbase + K5_B_OFF(buf^1) + dsto[i], srcB[i] + (kt+1)*32);
            }
            CP_COMMIT();
            asm volatile("cp.async.wait_group 1;" ::: "memory");
        } else {
            asm volatile("cp.async.wait_group 0;" ::: "memory");
        }
        __syncthreads();

        const float* As = smem + (K5_A_OFF(buf) >> 2);
        const float* Bs = smem + (K5_B_OFF(buf) >> 2);
#pragma unroll
        for (int ks = 0; ks < 4; ks++) {
            wmma::fragment<wmma::matrix_a, 16, 16, 8, wmma::precision::tf32, wmma::row_major> af[4];
            wmma::fragment<wmma::matrix_b, 16, 16, 8, wmma::precision::tf32, wmma::col_major> bf[2];
#pragma unroll
            for (int mi = 0; mi < 4; mi++) {
                wmma::load_matrix_sync(af[mi], As + (warp_m*64 + mi*16)*K5_AS + ks*8, K5_AS);
#pragma unroll
                for (int e = 0; e < af[mi].num_elements; e++)
                    af[mi].x[e] = wmma::__float_to_tf32(af[mi].x[e]);
            }
#pragma unroll
            for (int ni = 0; ni < 2; ni++) {
                wmma::load_matrix_sync(bf[ni], Bs + (warp_n*32 + ni*16)*K5_AS + ks*8, K5_AS);
#pragma unroll
                for (int e = 0; e < bf[ni].num_elements; e++)
                    bf[ni].x[e] = wmma::__float_to_tf32(bf[ni].x[e]);
            }
#pragma unroll
            for (int mi = 0; mi < 4; mi++)
#pragma unroll
                for (int ni = 0; ni < 2; ni++)
                    wmma::mma_sync(cf[mi][ni], af[mi], bf[ni], cf[mi][ni]);
        }
        __syncthreads();
        buf ^= 1;
    }

    // stage accumulators into smem (reuses pipeline smem)
#pragma unroll
    for (int mi = 0; mi < 4; mi++)
#pragma unroll
        for (int ni = 0; ni < 2; ni++)
            wmma::store_matrix_sync(smem + (warp_m*64 + mi*16)*K5_CS + warp_n*32 + ni*16,
                                    cf[mi][ni], K5_CS, wmma::mem_row_major);
    __syncthreads();

    // fused epilogue: 4096 float4, 16 per thread
    int b = rowBase >> 10;
    const float* gs = g_gsem + b*DV;
    const float* at = g_att + b*DV;
#pragma unroll
    for (int j = 0; j < 16; j++) {
        int idx = tid + j*256;          // float4 index
        int row = idx >> 5, c4 = idx & 31;
        int r = rowBase + row;
        int c = colBase + c4*4;
        const float* Cr = smem + row*K5_CS + c4*4;
        float4 av = *(const float4*)(A + (size_t)r*DV + c);
        float4 o;
        o.x = av.x + at[c+0] * (1.f/(1.f + __expf(-(Cr[0] + gs[c+0]))));
        o.y = av.y + at[c+1] * (1.f/(1.f + __expf(-(Cr[1] + gs[c+1]))));
        o.z = av.z + at[c+2] * (1.f/(1.f + __expf(-(Cr[2] + gs[c+2]))));
        o.w = av.w + at[c+3] * (1.f/(1.f + __expf(-(Cr[3] + gs[c+3]))));
        *(float4*)(out + (size_t)r*DV + c) = o;
    }
}

// ---------------- launcher ----------------
extern "C" void kernel_launch(void* const* d_in, const int* in_sizes, int n_in,
                              void* d_out, int out_size) {
    const float* visual   = (const float*)d_in[0];
    const float* semantic = (const float*)d_in[1];
    const float* Wq = (const float*)d_in[2];
    const float* Wk = (const float*)d_in[3];
    const float* Wv = (const float*)d_in[4];
    const float* Wo = (const float*)d_in[5];
    const float* bo = (const float*)d_in[6];
    const float* Wg = (const float*)d_in[7];
    const float* bg = (const float*)d_in[8];
    const float* gv = (const float*)d_in[9];
    const float* bv = (const float*)d_in[10];
    const float* gs = (const float*)d_in[11];
    const float* bs = (const float*)d_in[12];
    float* out = (float*)d_out;

    cudaFuncSetAttribute(k5, cudaFuncAttributeMaxDynamicSharedMemorySize, K5_SMEM_TOTAL);

    k0a<<<BB, 256>>>(semantic, Wq, gs, bs);
    k0b<<<dim3(HH, BB), 256>>>(Wk, gv, bv);
    k0c<<<BB, 256>>>(semantic, Wg, bg);
    k1<<<ROWS/32, 256>>>(visual);
    k2<<<BB*HH, 256>>>();
    k3<<<dim3(NCHUNK, BB), 768>>>(visual);
    k3b<<<(BB*HH*DV)/1024, 1024>>>();
    k4a<<<dim3(HH, BB), 256>>>(Wv, gv, bv);
    k4b<<<BB, 256>>>(Wo, bo);
    k5<<<dim3(ROWS/128, DV/128), 256, K5_SMEM_TOTAL>>>(visual, Wg, out);
}

// round 4
// speedup vs baseline: 1.5912x; 1.5912x over previous
#include <cuda_runtime.h>
#include <math.h>
#include <stdint.h>

// ---------------- problem constants ----------------
#define BB 8
#define NN 1024
#define DV 768
#define DS 512
#define FF 768
#define HH 12
#define DH 64
#define KG 1280        // Dv + Ds
#define ROWS (BB*NN)   // 8192
#define SCALE 0.125f   // dh^-0.5
#define EPS 1e-5f

// ---------------- scratch (device globals; no allocation allowed) ----------------
__device__ float g_q[BB*FF];
__device__ float g_gw[BB*HH*DV];      // scale * gv[d] * wqk[b,h,d]
__device__ float g_S1[BB*HH];         // sum_d gw
__device__ float g_S0[BB*HH];         // scale * sum_d bv[d]*wqk
__device__ float g_gsem[BB*DV];       // sem @ Wg[:,768:].T + bg
__device__ float g_mu[ROWS];
__device__ float g_rstd[ROWS];
__device__ float g_scores[BB*HH*NN];
__device__ float g_w[BB*HH*NN];       // attn * rstd
__device__ float g_t[BB*HH];          // sum_n attn*rstd*mu
#define NCHUNK 32
__device__ float g_vbarp[NCHUNK*BB*HH*DV];
__device__ float g_vbar[BB*HH*DV];
__device__ float g_ctx[BB*FF];
__device__ float g_att[BB*DV];

// ---------------- generic helpers ----------------
__device__ __forceinline__ float warp_sum(float v) {
#pragma unroll
    for (int o = 16; o > 0; o >>= 1) v += __shfl_down_sync(0xffffffffu, v, o);
    return v;
}
__device__ __forceinline__ float warp_sum_all(float v) {
#pragma unroll
    for (int o = 16; o > 0; o >>= 1) v += __shfl_xor_sync(0xffffffffu, v, o);
    return v;
}
__device__ __forceinline__ float warp_max(float v) {
#pragma unroll
    for (int o = 16; o > 0; o >>= 1) v = fmaxf(v, __shfl_down_sync(0xffffffffu, v, o));
    return v;
}
__device__ __forceinline__ float block_sum256(float v, float* red) {
    int lane = threadIdx.x & 31, wid = threadIdx.x >> 5;
    __syncthreads();
    v = warp_sum(v);
    if (lane == 0) red[wid] = v;
    __syncthreads();
    if (wid == 0) {
        float x = (lane < 8) ? red[lane] : 0.f;
        x = warp_sum(x);
        if (lane == 0) red[0] = x;
    }
    __syncthreads();
    return red[0];
}
__device__ __forceinline__ float block_max256(float v, float* red) {
    int lane = threadIdx.x & 31, wid = threadIdx.x >> 5;
    __syncthreads();
    v = warp_max(v);
    if (lane == 0) red[wid] = v;
    __syncthreads();
    if (wid == 0) {
        float x = (lane < 8) ? red[lane] : -1e30f;
        x = warp_max(x);
        if (lane == 0) red[0] = x;
    }
    __syncthreads();
    return red[0];
}

#define CP16(dst, src)   asm volatile("cp.async.cg.shared.global [%0], [%1], 16;" :: "r"(dst), "l"(src) : "memory")
#define CP_COMMIT()      asm volatile("cp.async.commit_group;" ::: "memory")

__device__ __forceinline__ uint32_t smem_u32(const void* p) {
    uint32_t a;
    asm("{ .reg .u64 t; cvta.to.shared.u64 t, %1; cvt.u32.u64 %0, t; }" : "=r"(a) : "l"(p));
    return a;
}

// m16n8k8 tf32 mma (row.col), D = A*B + D. Operands hold raw fp32 bits
// (HW consumes the tf32 subset; truncation error ~2^-10, far under tolerance).
__device__ __forceinline__ void mma_tf32(float* c, const uint32_t* a, const uint32_t* b) {
    asm volatile(
        "mma.sync.aligned.m16n8k8.row.col.f32.tf32.tf32.f32 "
        "{%0,%1,%2,%3}, {%4,%5,%6,%7}, {%8,%9}, {%0,%1,%2,%3};"
        : "+f"(c[0]), "+f"(c[1]), "+f"(c[2]), "+f"(c[3])
        : "r"(a[0]), "r"(a[1]), "r"(a[2]), "r"(a[3]), "r"(b[0]), "r"(b[1]));
}

// ---------------- K0a: semantic LN + q = sem_n @ Wq.T ----------------
__global__ __launch_bounds__(256) void k0a(const float* __restrict__ sem,
                                           const float* __restrict__ Wq,
                                           const float* __restrict__ gs,
                                           const float* __restrict__ bs) {
    int b = blockIdx.x;
    __shared__ float sm[DS];
    __shared__ float red[8];
    int tid = threadIdx.x, lane = tid & 31, wid = tid >> 5;
    float sum = 0.f, sq = 0.f;
    for (int i = tid; i < DS; i += 256) {
        float v = sem[b*DS + i];
        sm[i] = v; sum += v; sq += v*v;
    }
    sum = block_sum256(sum, red);
    sq  = block_sum256(sq, red);
    float mu = sum * (1.f/DS);
    float rstd = rsqrtf(sq * (1.f/DS) - mu*mu + EPS);
    for (int i = tid; i < DS; i += 256)
        sm[i] = (sm[i] - mu) * rstd * gs[i] + bs[i];
    __syncthreads();
    for (int f = wid; f < FF; f += 8) {
        float dot = 0.f;
        for (int s = lane; s < DS; s += 32) dot += sm[s] * Wq[(size_t)f*DS + s];
        dot = warp_sum(dot);
        if (lane == 0) g_q[b*FF + f] = dot;
    }
}

// ---------------- K0b: gw[b,h,:] = scale*gv*(q_h @ Wk_h), S1, S0 ----------------
__global__ __launch_bounds__(256) void k0b(const float* __restrict__ Wk,
                                           const float* __restrict__ gv,
                                           const float* __restrict__ bv) {
    int h = blockIdx.x, b = blockIdx.y;
    __shared__ float qh[DH];
    __shared__ float red[8];
    int tid = threadIdx.x;
    if (tid < DH) qh[tid] = g_q[b*FF + h*DH + tid];
    __syncthreads();
    float s1p = 0.f, s0p = 0.f;
    for (int d = tid; d < DV; d += 256) {
        float s = 0.f;
#pragma unroll 16
        for (int j = 0; j < DH; j++) s += qh[j] * Wk[(size_t)(h*DH + j)*DV + d];
        s *= SCALE;
        float gwv = gv[d] * s;
        g_gw[(b*HH + h)*DV + d] = gwv;
        s1p += gwv;
        s0p += bv[d] * s;
    }
    s1p = block_sum256(s1p, red);
    s0p = block_sum256(s0p, red);
    if (tid == 0) { g_S1[b*HH + h] = s1p; g_S0[b*HH + h] = s0p; }
}

// ---------------- K0c: gsem[b,:] = sem @ Wg[:,768:].T + bg ----------------
__global__ __launch_bounds__(256) void k0c(const float* __restrict__ sem,
                                           const float* __restrict__ Wg,
                                           const float* __restrict__ bg) {
    int b = blockIdx.x;
    __shared__ float sm[DS];
    int tid = threadIdx.x, lane = tid & 31, wid = tid >> 5;
    for (int i = tid; i < DS; i += 256) sm[i] = sem[b*DS + i];
    __syncthreads();
    for (int dv = wid; dv < DV; dv += 8) {
        float dot = 0.f;
        for (int s = lane; s < DS; s += 32) dot += sm[s] * Wg[(size_t)dv*KG + DV + s];
        dot = warp_sum(dot);
        if (lane == 0) g_gsem[b*DV + dv] = dot + bg[dv];
    }
}

// ---------------- K1: warp-per-row LN stats + scores (32 rows / block) ----------------
__global__ __launch_bounds__(256, 2) void k1(const float* __restrict__ vis) {
    __shared__ float gw_s[HH*DV];   // 36 KB
    __shared__ float s1s[HH], s0s[HH];
    int tid = threadIdx.x, lane = tid & 31, wid = tid >> 5;
    int row0 = blockIdx.x * 32;
    int b = row0 >> 10;
    {
        const float4* gsrc = (const float4*)(g_gw + b*HH*DV);
        float4* gdst = (float4*)gw_s;
#pragma unroll
        for (int i = 0; i < 9; i++) gdst[tid + i*256] = gsrc[tid + i*256];
    }
    if (tid < HH) { s1s[tid] = g_S1[b*HH + tid]; s0s[tid] = g_S0[b*HH + tid]; }
    __syncthreads();
#pragma unroll
    for (int rr = 0; rr < 4; rr++) {
        int row = row0 + wid*4 + rr;
        const float4* x4 = (const float4*)(vis + (size_t)row * DV);
        float4 xv[6];
#pragma unroll
        for (int s = 0; s < 6; s++) xv[s] = x4[s*32 + lane];
        float sum = 0.f, sq = 0.f;
#pragma unroll
        for (int s = 0; s < 6; s++) {
            sum += xv[s].x + xv[s].y + xv[s].z + xv[s].w;
            sq  += xv[s].x*xv[s].x + xv[s].y*xv[s].y + xv[s].z*xv[s].z + xv[s].w*xv[s].w;
        }
        sum = warp_sum_all(sum);
        sq  = warp_sum_all(sq);
        float mu = sum * (1.f/DV);
        float rstd = rsqrtf(sq * (1.f/DV) - mu*mu + EPS);
        if (lane == 0) { g_mu[row] = mu; g_rstd[row] = rstd; }
        int n = row & (NN - 1);
#pragma unroll 2
        for (int h = 0; h < HH; h++) {
            const float4* g4 = (const float4*)(gw_s + h*DV);
            float dot = 0.f;
#pragma unroll
            for (int s = 0; s < 6; s++) {
                float4 gv4 = g4[s*32 + lane];
                dot += xv[s].x*gv4.x + xv[s].y*gv4.y + xv[s].z*gv4.z + xv[s].w*gv4.w;
            }
            dot = warp_sum(dot);
            if (lane == 0)
                g_scores[(b*HH + h)*NN + n] = rstd * (dot - mu*s1s[h]) + s0s[h];
        }
    }
}

// ---------------- K2: softmax over n; w = attn*rstd, t = sum attn*rstd*mu ----------------
__global__ __launch_bounds__(256) void k2() {
    int bh = blockIdx.x;
    int b = bh / HH;
    __shared__ float red[8];
    int tid = threadIdx.x;
    float loc[4];
    float mx = -1e30f;
#pragma unroll
    for (int i = 0; i < 4; i++) {
        loc[i] = g_scores[bh*NN + tid + i*256];
        mx = fmaxf(mx, loc[i]);
    }
    mx = block_max256(mx, red);
    float s = 0.f;
#pragma unroll
    for (int i = 0; i < 4; i++) { loc[i] = expf(loc[i] - mx); s += loc[i]; }
    s = block_sum256(s, red);
    float inv = 1.f / s;
    float tp = 0.f;
#pragma unroll
    for (int i = 0; i < 4; i++) {
        int n = tid + i*256;
        float a = loc[i] * inv;
        float rs = g_rstd[b*NN + n];
        float w = a * rs;
        g_w[bh*NN + n] = w;
        tp += w * g_mu[b*NN + n];
    }
    tp = block_sum256(tp, red);
    if (tid == 0) g_t[bh] = tp;
}

// ---------------- K3: per-chunk partial vbar (deterministic) ----------------
__global__ __launch_bounds__(768) void k3(const float* __restrict__ vis) {
    int chunk = blockIdx.x;     // 32 chunks of 32 tokens
    int b = blockIdx.y;
    int d = threadIdx.x;        // 768 threads = one per feature
    __shared__ float ws[HH][32];
    int n0 = chunk * 32;
    if (d < HH*32) {
        int h = d >> 5, j = d & 31;
        ws[h][j] = g_w[(b*HH + h)*NN + n0 + j];
    }
    __syncthreads();
    float acc[HH];
#pragma unroll
    for (int h = 0; h < HH; h++) acc[h] = 0.f;
    const float* base = vis + ((size_t)(b << 10) + n0) * DV + d;
#pragma unroll 4
    for (int j = 0; j < 32; j++) {
        float x = base[(size_t)j * DV];
#pragma unroll
        for (int h = 0; h < HH; h++) acc[h] += ws[h][j] * x;
    }
#pragma unroll
    for (int h = 0; h < HH; h++)
        g_vbarp[(size_t)chunk*(BB*HH*DV) + (b*HH + h)*DV + d] = acc[h];
}

// ---------------- K3b: reduce chunks ----------------
__global__ __launch_bounds__(1024) void k3b() {
    int i = blockIdx.x * 1024 + threadIdx.x;
    float s = 0.f;
#pragma unroll
    for (int c = 0; c < NCHUNK; c++) s += g_vbarp[(size_t)c*(BB*HH*DV) + i];
    g_vbar[i] = s;
}

// ---------------- K4a: ctx[b,f] = u[b,h,:] @ Wv[f,:] ----------------
__global__ __launch_bounds__(256) void k4a(const float* __restrict__ Wv,
                                           const float* __restrict__ gv,
                                           const float* __restrict__ bv) {
    int h = blockIdx.x, b = blockIdx.y;
    __shared__ float u[DV];
    int tid = threadIdx.x, lane = tid & 31, wid = tid >> 5;
    float t = g_t[b*HH + h];
    for (int d = tid; d < DV; d += 256)
        u[d] = gv[d] * (g_vbar[(b*HH + h)*DV + d] - t) + bv[d];
    __syncthreads();
    for (int j = wid; j < DH; j += 8) {
        int f = h*DH + j;
        float dot = 0.f;
        for (int d = lane; d < DV; d += 32) dot += u[d] * Wv[(size_t)f*DV + d];
        dot = warp_sum(dot);
        if (lane == 0) g_ctx[b*FF + f] = dot;
    }
}

// ---------------- K4b: attended[b,:] = ctx @ Wo.T + bo ----------------
__global__ __launch_bounds__(256) void k4b(const float* __restrict__ Wo,
                                           const float* __restrict__ bo) {
    int b = blockIdx.x;
    __shared__ float c[FF];
    int tid = threadIdx.x, lane = tid & 31, wid = tid >> 5;
    for (int i = tid; i < FF; i += 256) c[i] = g_ctx[b*FF + i];
    __syncthreads();
    for (int dv = wid; dv < DV; dv += 8) {
        float dot = 0.f;
        for (int f = lane; f < FF; f += 32) dot += c[f] * Wo[(size_t)dv*FF + f];
        dot = warp_sum(dot);
        if (lane == 0) g_att[b*DV + dv] = dot + bo[dv];
    }
}

// ---------------- K5: gate GEMM (mma.sync tf32) + fused sigmoid/residual epilogue ----------------
// out[r,c] = A[r,c] + sigmoid( sum_k A[r,k]*Wg[c,k] + gsem[b,c] ) * att[b,c]
// CTA tile M=128, N=128; K=768 in 24 tiles of 32 (4 k-steps of 8).
// 2-stage cp.async double buffer. 8 warps in 2(M)x4(N); each warp 64x32 via
// mma.m16n8k8 tf32 (4 m-frags x 4 n-frags). smem stride 36 floats ->
// fragment-load bank index (4g+tig) mod 32: conflict-free.

#define K5_LDA 36
#define K5_TILE_BYTES (128*K5_LDA*4)       // 18432
#define K5_A_OFF(s) ((s)*2*K5_TILE_BYTES)
#define K5_B_OFF(s) ((s)*2*K5_TILE_BYTES + K5_TILE_BYTES)
#define K5_SMEM_TOTAL (4*K5_TILE_BYTES)    // 73728; reused for C staging
#define K5_CS 132

__global__ void __launch_bounds__(256, 2)
k5(const float* __restrict__ A, const float* __restrict__ Wg, float* __restrict__ out) {
    extern __shared__ float smem[];
    uint32_t sbase = smem_u32(smem);
    int tid = threadIdx.x, wid = tid >> 5, lane = tid & 31;
    int rowBase = blockIdx.x * 128;
    int colBase = blockIdx.y * 128;
    int warp_m = wid >> 2;       // 0..1 -> 64 rows
    int warp_n = wid & 3;        // 0..3 -> 32 cols
    int g = lane >> 2, tig = lane & 3;

    // per-thread cp.async slots: 4 x 16B for A, 4 x 16B for B per stage
    uint32_t dsto[4];
    const float* srcA[4];
    const float* srcB[4];
#pragma unroll
    for (int i = 0; i < 4; i++) {
        int idx = tid + i*256;           // 0..1023
        int row = idx >> 3, seg = idx & 7;
        dsto[i] = (uint32_t)((row*K5_LDA + seg*4) * 4);
        srcA[i] = A  + (size_t)(rowBase + row)*DV + seg*4;
        srcB[i] = Wg + (size_t)(colBase + row)*KG + seg*4;
    }

    float cf[4][4][4];
#pragma unroll
    for (int mi = 0; mi < 4; mi++)
#pragma unroll
        for (int ni = 0; ni < 4; ni++)
#pragma unroll
            for (int e = 0; e < 4; e++) cf[mi][ni][e] = 0.f;

    // prologue: stage 0
#pragma unroll
    for (int i = 0; i < 4; i++) {
        CP16(sbase + K5_A_OFF(0) + dsto[i], srcA[i]);
        CP16(sbase + K5_B_OFF(0) + dsto[i], srcB[i]);
    }
    CP_COMMIT();

    int buf = 0;
    for (int kt = 0; kt < 24; kt++) {
        if (kt + 1 < 24) {
#pragma unroll
            for (int i = 0; i < 4; i++) {
                CP16(sbase + K5_A_OFF(buf^1) + dsto[i], srcA[i] + (kt+1)*32);
                CP16(sbase + K5_B_OFF(buf^1) + dsto[i], srcB[i] + (kt+1)*32);
            }
            CP_COMMIT();
            asm volatile("cp.async.wait_group 1;" ::: "memory");
        } else {
            asm volatile("cp.async.wait_group 0;" ::: "memory");
        }
        __syncthreads();

        const float* As = smem + (K5_A_OFF(buf) >> 2);
        const float* Bs = smem + (K5_B_OFF(buf) >> 2);
#pragma unroll
        for (int ks = 0; ks < 4; ks++) {
            int k0 = ks*8;
            uint32_t af[4][4], bfr[4][2];
#pragma unroll
            for (int mi = 0; mi < 4; mi++) {
                int r0 = warp_m*64 + mi*16 + g;
                af[mi][0] = __float_as_uint(As[r0*K5_LDA + k0 + tig]);
                af[mi][1] = __float_as_uint(As[(r0+8)*K5_LDA + k0 + tig]);
                af[mi][2] = __float_as_uint(As[r0*K5_LDA + k0 + tig + 4]);
                af[mi][3] = __float_as_uint(As[(r0+8)*K5_LDA + k0 + tig + 4]);
            }
#pragma unroll
            for (int ni = 0; ni < 4; ni++) {
                int c0 = warp_n*32 + ni*8 + g;
                bfr[ni][0] = __float_as_uint(Bs[c0*K5_LDA + k0 + tig]);
                bfr[ni][1] = __float_as_uint(Bs[c0*K5_LDA + k0 + tig + 4]);
            }
#pragma unroll
            for (int mi = 0; mi < 4; mi++)
#pragma unroll
                for (int ni = 0; ni < 4; ni++)
                    mma_tf32(cf[mi][ni], af[mi], bfr[ni]);
        }
        __syncthreads();
        buf ^= 1;
    }

    // stage accumulators into smem (reuses pipeline smem)
    // thread holds: rows {r0, r0+8}, cols {2*tig, 2*tig+1} per (mi,ni)
#pragma unroll
    for (int mi = 0; mi < 4; mi++) {
        int r0 = warp_m*64 + mi*16 + g;
#pragma unroll
        for (int ni = 0; ni < 4; ni++) {
            int c0 = warp_n*32 + ni*8 + 2*tig;
            smem[r0*K5_CS + c0]       = cf[mi][ni][0];
            smem[r0*K5_CS + c0 + 1]   = cf[mi][ni][1];
            smem[(r0+8)*K5_CS + c0]     = cf[mi][ni][2];
            smem[(r0+8)*K5_CS + c0 + 1] = cf[mi][ni][3];
        }
    }
    __syncthreads();

    // fused epilogue: 4096 float4, 16 per thread
    int b = rowBase >> 10;
    const float* gs = g_gsem + b*DV;
    const float* at = g_att + b*DV;
#pragma unroll
    for (int j = 0; j < 16; j++) {
        int idx = tid + j*256;          // float4 index
        int row = idx >> 5, c4 = idx & 31;
        int r = rowBase + row;
        int c = colBase + c4*4;
        const float* Cr = smem + row*K5_CS + c4*4;
        float4 av = *(const float4*)(A + (size_t)r*DV + c);
        float4 o;
        o.x = av.x + at[c+0] * (1.f/(1.f + __expf(-(Cr[0] + gs[c+0]))));
        o.y = av.y + at[c+1] * (1.f/(1.f + __expf(-(Cr[1] + gs[c+1]))));
        o.z = av.z + at[c+2] * (1.f/(1.f + __expf(-(Cr[2] + gs[c+2]))));
        o.w = av.w + at[c+3] * (1.f/(1.f + __expf(-(Cr[3] + gs[c+3]))));
        *(float4*)(out + (size_t)r*DV + c) = o;
    }
}

// ---------------- launcher ----------------
extern "C" void kernel_launch(void* const* d_in, const int* in_sizes, int n_in,
                              void* d_out, int out_size) {
    const float* visual   = (const float*)d_in[0];
    const float* semantic = (const float*)d_in[1];
    const float* Wq = (const float*)d_in[2];
    const float* Wk = (const float*)d_in[3];
    const float* Wv = (const float*)d_in[4];
    const float* Wo = (const float*)d_in[5];
    const float* bo = (const float*)d_in[6];
    const float* Wg = (const float*)d_in[7];
    const float* bg = (const float*)d_in[8];
    const float* gv = (const float*)d_in[9];
    const float* bv = (const float*)d_in[10];
    const float* gs = (const float*)d_in[11];
    const float* bs = (const float*)d_in[12];
    float* out = (float*)d_out;

    cudaFuncSetAttribute(k5, cudaFuncAttributeMaxDynamicSharedMemorySize, K5_SMEM_TOTAL);

    k0a<<<BB, 256>>>(semantic, Wq, gs, bs);
    k0b<<<dim3(HH, BB), 256>>>(Wk, gv, bv);
    k0c<<<BB, 256>>>(semantic, Wg, bg);
    k1<<<ROWS/32, 256>>>(visual);
    k2<<<BB*HH, 256>>>();
    k3<<<dim3(NCHUNK, BB), 768>>>(visual);
    k3b<<<(BB*HH*DV)/1024, 1024>>>();
    k4a<<<dim3(HH, BB), 256>>>(Wv, gv, bv);
    k4b<<<BB, 256>>>(Wo, bo);
    k5<<<dim3(ROWS/128, DV/128), 256, K5_SMEM_TOTAL>>>(visual, Wg, out);
}